// round 16
// baseline (speedup 1.0000x reference)
#include <cuda_runtime.h>
#include <math.h>
#include <stdint.h>

// ---------------------------------------------------------------------------
// GATNE forward v10 — decoupled dependency chain:
//   k1 (k_gather_scan) : block0 = partition scan; rest = neighbor gather
//   k2 (k_fused)       : trans CTAs (mem-bound) + text-base GEMM CTAs
//                        (fma-bound) in ONE launch -> pipe overlap.
//                        text gemm: A=textF rows, B=text_embed, K=768,
//                        K-split x6 -> g_part
//   k3 (k_final)       : per row: agg@trans_w (+ userF@user_embed for user
//                        rows) + sum partials + L2-normalize + write
// ---------------------------------------------------------------------------

#define EMB       200
#define EMBU      20
#define TEXT_DIM  768
#define USER_DIM  32
#define NSLOT     10
#define B_MAX     4096
#define NCHUNK    6            // text K-split: 768 = 6 chunks x 128 (4 tiles x 32)

// k2 gemm smem layout (floats)
#define AM_LD     36
#define AM_BUF    (64 * AM_LD)            // 2304
#define BS_BUF    (32 * EMB)              // 6400
#define K2_OFF_BS (2 * AM_BUF)            // 4608
#define K2_OFF_TF (K2_OFF_BS + 2 * BS_BUF)// 17408
#define K2_SMEM   (K2_OFF_TF + 64)        // 17472 floats

// k2 trans smem layout (floats) — unioned with gemm layout
#define TR_ROWS   20
#define TR_OFF_NTE (TEXT_DIM * EMBU)          // 15360
#define TR_OFF_ROW (TR_OFF_NTE + TR_ROWS * 40)// 16160
#define TR_SMEM    (TR_OFF_ROW + TR_ROWS)     // 16180

// k3 smem layout (floats)
#define K3_OFF_UW  (40 * EMB)              // 8000
#define K3_OFF_AGG (K3_OFF_UW + 32 * EMB)  // 14400
#define K3_OFF_UF  (K3_OFF_AGG + 32 * 40)  // 15680
#define K3_OFF_ROW (K3_OFF_UF + 32 * 32)   // 16704
#define K3_OFF_IDX (K3_OFF_ROW + 32)       // 16736
#define K3_SMEM    (K3_OFF_IDX + 32)       // 16768

// ------------------------- device scratch ----------------------------------
__device__ int    g_rowmap[B_MAX];
__device__ int    g_tmap[B_MAX];
__device__ int    g_nuser;
__device__ int    g_ntype0;
__device__ float  g_agg[B_MAX * 40];
__device__ float4 g_nsum4[B_MAX * 2 * (TEXT_DIM / 4)];
__device__ float  g_part[(size_t)NCHUNK * B_MAX * EMB];

// ------------------------- cp.async helpers ---------------------------------
__device__ __forceinline__ void cp16(void* dst, const void* src)
{
    uint32_t d = (uint32_t)__cvta_generic_to_shared(dst);
    asm volatile("cp.async.cg.shared.global [%0], [%1], 16;\n"
                 :: "r"(d), "l"(src));
}
__device__ __forceinline__ void cp_commit()
{
    asm volatile("cp.async.commit_group;\n");
}
template<int N> __device__ __forceinline__ void cp_wait()
{
    asm volatile("cp.async.wait_group %0;\n" :: "n"(N));
}

// ------------------------- k1: gather + fused scan ---------------------------
__global__ __launch_bounds__(256) void k_gather_scan(
    const int*   __restrict__ train_types,
    const int*   __restrict__ node_neigh,
    const float* __restrict__ neigh_features,
    const int*   __restrict__ indices,
    int B, int NU)
{
    int tid  = threadIdx.x;
    int lane = tid & 31;
    int wid  = tid >> 5;

    if (blockIdx.x == 0) {
        __shared__ int wsU[8], wsT[8];
        const int CH = 16;
        int b0 = tid * CH;
        int idxv[CH], tyv[CH];
        int cu = 0, ct = 0;
#pragma unroll
        for (int j = 0; j < CH; j++) {
            int b = b0 + j;
            if (b < B) {
                idxv[j] = indices[b];
                tyv[j]  = train_types[b];
                cu += (idxv[j] < NU);
                ct += (tyv[j] == 0);
            }
        }
        int xu = cu, xt = ct;
        for (int o = 1; o < 32; o <<= 1) {
            int yu = __shfl_up_sync(0xffffffffu, xu, o);
            int yt = __shfl_up_sync(0xffffffffu, xt, o);
            if (lane >= o) { xu += yu; xt += yt; }
        }
        if (lane == 31) { wsU[wid] = xu; wsT[wid] = xt; }
        __syncthreads();
        int baseU = 0, baseT = 0, totU = 0, totT = 0;
#pragma unroll
        for (int i = 0; i < 8; i++) {
            if (i < wid) { baseU += wsU[i]; baseT += wsT[i]; }
            totU += wsU[i]; totT += wsT[i];
        }
        int uRun = (xu - cu) + baseU;
        int tRun = (xt - ct) + baseT;
#pragma unroll
        for (int j = 0; j < CH; j++) {
            int b = b0 + j;
            if (b >= B) break;
            if (idxv[j] < NU) g_rowmap[uRun++] = b;
            else              g_rowmap[totU + (b - uRun)] = b;
            if (tyv[j] == 0)  g_tmap[tRun++] = b;
            else              g_tmap[totT + (b - tRun)] = b;
        }
        if (tid == 0) { g_nuser = totU; g_ntype0 = totT; }
        return;
    }

    int gw = (blockIdx.x - 1) * 8 + wid;
    int b  = gw >> 1;
    int t  = gw & 1;
    if (b >= B) return;

    int ty = train_types[b];
    int nn_l = 0;
    if (lane < NSLOT)
        nn_l = node_neigh[(size_t)(b * 2 + t) * NSLOT + lane];

    const float4* nf4 = (const float4*)neigh_features;
    float4* dst = g_nsum4 + (size_t)(b * 2 + t) * 192;

    if (ty == 1) {
#pragma unroll 2
        for (int c = 0; c < 6; c++) {
            int k4 = c * 32 + lane;
            float4 acc = make_float4(0.f, 0.f, 0.f, 0.f);
#pragma unroll
            for (int s = 0; s < NSLOT; s++) {
                int idx = __shfl_sync(0xffffffffu, nn_l, s);
                float4 v = nf4[(size_t)idx * 192 + k4];
                acc.x += v.x; acc.y += v.y; acc.z += v.z; acc.w += v.w;
            }
            dst[k4] = acc;
        }
    } else {
        float4 acc = make_float4(0.f, 0.f, 0.f, 0.f);
#pragma unroll
        for (int s = 0; s < NSLOT; s++) {
            int idx = __shfl_sync(0xffffffffu, nn_l, s);
            if (lane < 8) {
                float4 v = nf4[(size_t)idx * 192 + lane];
                acc.x += v.x; acc.y += v.y; acc.z += v.z; acc.w += v.w;
            }
        }
        if (lane < 8) dst[lane] = acc;
    }
}

// ------------------------- k2: fused trans + text-base GEMM ------------------
// Grid: [0, 2*Ttr) trans CTAs (20 rows each, 10 warps x 2 rows);
//       [2*Ttr, ..) text-base gemm CTAs (64 rows x 6 K-chunks of 128).
__global__ __launch_bounds__(320, 2) void k_fused(
    const float* __restrict__ tweet_u,
    const float* __restrict__ user_u,
    const float* __restrict__ s1,
    const float* __restrict__ s2,
    const int*   __restrict__ indices,
    const float* __restrict__ text_features,
    const float* __restrict__ text_embed,
    int B, int NU, int Ttr)
{
    extern __shared__ float sm[];
    int tid  = threadIdx.x;
    int wid  = tid >> 5;
    int lane = tid & 31;
    int bx   = blockIdx.x;

    if (bx < 2 * Ttr) {
        // =================== TRANS path ===================
        float* U1  = sm;                   // [F][20]
        float* nte = sm + TR_OFF_NTE;      // [20][40]
        int*  srow = (int*)(sm + TR_OFF_ROW);

        int ty   = (bx >= Ttr) ? 1 : 0;
        int tile = ty ? (bx - Ttr) : bx;
        int n0   = g_ntype0;
        int base = ty ? n0 : 0;
        int cnt  = ty ? (B - n0) : n0;
        int m0   = tile * TR_ROWS;
        if (m0 >= cnt) return;

        int F = ty ? TEXT_DIM : USER_DIM;
        const float* Usrc = ty ? tweet_u : user_u;

        if (tid < TR_ROWS) {
            int mm = m0 + tid; if (mm > cnt - 1) mm = cnt - 1;
            srow[tid] = g_tmap[base + mm];
        }

        int i0 = 2 * wid;                  // rows i0, i0+1 (wid 0..9)
        const float* ns = (const float*)g_nsum4;

        for (int t = 0; t < 2; t++) {
            __syncthreads();
            {
                int cnt4 = (F * EMBU) / 4;
                const float4* src = (const float4*)(Usrc + (size_t)t * F * EMBU);
                float4* d = (float4*)U1;
                for (int i = tid; i < cnt4; i += 320) d[i] = src[i];
            }
            __syncthreads();

            int b0 = srow[i0], b1 = srow[i0 + 1];
            float accA[EMBU], accB[EMBU];
#pragma unroll
            for (int u = 0; u < EMBU; u++) { accA[u] = 0.f; accB[u] = 0.f; }
            const float* ns0 = ns + (size_t)(b0 * 2 + t) * TEXT_DIM;
            const float* ns1 = ns + (size_t)(b1 * 2 + t) * TEXT_DIM;

            for (int k = lane; k < F; k += 32) {
                float a0 = ns0[k];
                float a1 = ns1[k];
                const float4* Urow = (const float4*)(U1 + k * EMBU);
#pragma unroll
                for (int q = 0; q < 5; q++) {
                    float4 uv = Urow[q];
                    accA[q*4+0] += a0 * uv.x; accB[q*4+0] += a1 * uv.x;
                    accA[q*4+1] += a0 * uv.y; accB[q*4+1] += a1 * uv.y;
                    accA[q*4+2] += a0 * uv.z; accB[q*4+2] += a1 * uv.z;
                    accA[q*4+3] += a0 * uv.w; accB[q*4+3] += a1 * uv.w;
                }
            }
#pragma unroll
            for (int u = 0; u < EMBU; u++) {
                float rA = accA[u], rB = accB[u];
                for (int o = 16; o; o >>= 1) {
                    rA += __shfl_xor_sync(0xffffffffu, rA, o);
                    rB += __shfl_xor_sync(0xffffffffu, rB, o);
                }
                if (lane == 0) {
                    nte[i0 * 40 + t * EMBU + u] = rA;
                    nte[(i0 + 1) * 40 + t * EMBU + u] = rB;
                }
            }
        }
        __syncthreads();

        // attention: warp w handles rows w, w+10
        const float* S1 = s1 + ty * (EMBU * EMBU);
        const float* S2 = s2 + ty * EMBU;
        for (int g = wid; g < TR_ROWS; g += 10) {
            if (m0 + g >= cnt) continue;
            int b = srow[g];
            float sc[2];
#pragma unroll
            for (int t = 0; t < 2; t++) {
                float h = 0.f;
                if (lane < EMBU) {
#pragma unroll
                    for (int u = 0; u < EMBU; u++)
                        h += nte[g * 40 + t * EMBU + u] * S1[u * EMBU + lane];
                    h = tanhf(h) * S2[lane];
                }
                for (int o = 16; o; o >>= 1) h += __shfl_xor_sync(0xffffffffu, h, o);
                sc[t] = h;
            }
            float m  = fmaxf(sc[0], sc[1]);
            float e0 = expf(sc[0] - m);
            float e1 = expf(sc[1] - m);
            float inv = 1.f / (e0 + e1);
            float a0 = e0 * inv, a1 = e1 * inv;
            for (int l = lane; l < 40; l += 32) {
                float v = 0.f;
                if ((l / EMBU) == ty) {
                    int u = l - (l / EMBU) * EMBU;
                    v = a0 * nte[g * 40 + u] + a1 * nte[g * 40 + EMBU + u];
                }
                g_agg[(size_t)b * 40 + l] = v;
            }
        }
        return;
    }

    // =================== TEXT-BASE GEMM path ===================
    float* Am  = sm;                       // [2][64][AM_LD]
    float* Bs  = sm + K2_OFF_BS;           // [2][32][EMB]
    int*   stf = (int*)(sm + K2_OFF_TF);   // [64] text feature row

    int r = bx - 2 * Ttr;
    int tm = r / NCHUNK, chunk = r - tm * NCHUNK;
    int nuser = g_nuser;
    int cnt   = B - nuser;
    int m0    = tm * 64;
    if (m0 >= cnt) return;

    if (tid < 64) {
        int mm = m0 + tid; if (mm > cnt - 1) mm = cnt - 1;
        stf[tid] = indices[g_rowmap[nuser + mm]] - NU;
    }
    __syncthreads();

    int kbase = chunk * 128;

    auto loadA = [&](int t, int buf) {
        int k0 = kbase + t * 32;
        float* dstb = Am + buf * AM_BUF;
#pragma unroll
        for (int ii = 0; ii < 2; ii++) {
            int i = tid + ii * 320;
            if (i < 512) {
                int m  = i >> 3;
                int j4 = i & 7;
                cp16(dstb + m * AM_LD + j4 * 4,
                     text_features + (size_t)stf[m] * TEXT_DIM + k0 + j4 * 4);
            }
        }
    };
    auto loadB = [&](int t, int buf) {
        int k0 = kbase + t * 32;
        float* dstb = Bs + buf * BS_BUF;
        for (int i = tid; i < 1600; i += 320) {
            int k  = i / 50;
            int j4 = i - k * 50;
            cp16(dstb + k * EMB + j4 * 4,
                 text_embed + (size_t)(k0 + k) * EMB + j4 * 4);
        }
    };

    int rg = tid / 40;
    int cg = tid - rg * 40;

    float acc[8][5];
#pragma unroll
    for (int i = 0; i < 8; i++)
#pragma unroll
        for (int j = 0; j < 5; j++) acc[i][j] = 0.f;

    loadA(0, 0); loadB(0, 0); cp_commit();

    for (int t = 0; t < 4; t++) {
        int buf = t & 1;
        if (t + 1 < 4) {
            loadA(t + 1, buf ^ 1);
            loadB(t + 1, buf ^ 1);
            cp_commit();
            cp_wait<1>();
        } else {
            cp_wait<0>();
        }
        __syncthreads();

        const float* A  = Am + buf * AM_BUF + rg * 8 * AM_LD;
        const float* Bt = Bs + buf * BS_BUF + cg * 5;
#pragma unroll 4
        for (int k2 = 0; k2 < 16; k2++) {
            int k = 2 * k2;
            float2 a2[8];
#pragma unroll
            for (int i = 0; i < 8; i++)
                a2[i] = *(const float2*)(A + i * AM_LD + k);
            float b0[5], b1[5];
#pragma unroll
            for (int j = 0; j < 5; j++) {
                b0[j] = Bt[k * EMB + j];
                b1[j] = Bt[(k + 1) * EMB + j];
            }
#pragma unroll
            for (int i = 0; i < 8; i++)
#pragma unroll
                for (int j = 0; j < 5; j++)
                    acc[i][j] += a2[i].x * b0[j] + a2[i].y * b1[j];
        }
        __syncthreads();
    }

    float* pb = g_part + (size_t)chunk * B_MAX * EMB;
#pragma unroll
    for (int rr = 0; rr < 8; rr++) {
        int m = rg * 8 + rr;
        int mr = m0 + m;
        if (mr < cnt) {
            float* p = pb + (size_t)mr * EMB + cg * 5;
#pragma unroll
            for (int j = 0; j < 5; j++) p[j] = acc[rr][j];
        }
    }
}

// ------------------------- k3: finisher --------------------------------------
// CTA handles 32 rowmap positions: agg@trans_w (+ user base) + partials +
// L2-normalize + write.
__global__ __launch_bounds__(256) void k_final(
    float* __restrict__ out,
    const int*   __restrict__ indices,
    const float* __restrict__ user_features,
    const float* __restrict__ user_embed,
    const float* __restrict__ trans_w,
    int B, int NU)
{
    extern __shared__ float sm[];
    float* sTW  = sm;                      // [40][200]
    float* sUW  = sm + K3_OFF_UW;          // [32][200]
    float* sagg = sm + K3_OFF_AGG;         // [32][40]
    float* suf  = sm + K3_OFF_UF;          // [32][32]
    int*  srow  = (int*)(sm + K3_OFF_ROW); // [32]
    int*  sidx  = (int*)(sm + K3_OFF_IDX); // [32]

    int tid  = threadIdx.x;
    int wid  = tid >> 5;
    int lane = tid & 31;
    int p0   = blockIdx.x * 32;
    int nuser = g_nuser;

    if (tid < 32) {
        int p = p0 + tid; if (p > B - 1) p = B - 1;
        int b = g_rowmap[p];
        srow[tid] = b;
        sidx[tid] = indices[b];
    }
    for (int i = tid; i < 40 * EMB; i += 256) sTW[i] = trans_w[i];
    for (int i = tid; i < 32 * EMB; i += 256) sUW[i] = user_embed[i];
    __syncthreads();
    for (int i = tid; i < 32 * 40; i += 256)
        sagg[i] = g_agg[(size_t)srow[i / 40] * 40 + (i % 40)];
    for (int i = tid; i < 32 * 32; i += 256) {
        int rr = i >> 5;
        int idx = sidx[rr];
        suf[i] = (idx < NU) ? user_features[(size_t)idx * USER_DIM + (i & 31)] : 0.f;
    }
    __syncthreads();

    // warp w: rows 4w .. 4w+3
    for (int rr = 4 * wid; rr < 4 * wid + 4; rr++) {
        int p = p0 + rr;
        if (p >= B) continue;
        int b = srow[rr];
        bool isuser = (p < nuser);
        const float* ag = sagg + rr * 40;
        const float* uf = suf + rr * 32;

        float v[7];
        float ss = 0.f;
#pragma unroll
        for (int ii = 0; ii < 7; ii++) {
            int j = lane + 32 * ii;
            float val = 0.f;
            if (j < EMB) {
#pragma unroll
                for (int u = 0; u < 40; u++)
                    val += ag[u] * sTW[u * EMB + j];
                if (isuser) {
#pragma unroll
                    for (int k = 0; k < 32; k++)
                        val += uf[k] * sUW[k * EMB + j];
                } else {
                    size_t mr = (size_t)(p - nuser);
#pragma unroll
                    for (int c = 0; c < NCHUNK; c++)
                        val += g_part[((size_t)c * B_MAX + mr) * EMB + j];
                }
                ss += val * val;
            }
            v[ii] = val;
        }
        for (int o = 16; o; o >>= 1) ss += __shfl_xor_sync(0xffffffffu, ss, o);
        float sc = 1.f / fmaxf(sqrtf(ss), 1e-12f);
#pragma unroll
        for (int ii = 0; ii < 7; ii++) {
            int j = lane + 32 * ii;
            if (j < EMB) out[(size_t)b * EMB + j] = v[ii] * sc;
        }
    }
}

// ------------------------- launch ------------------------------------------
extern "C" void kernel_launch(void* const* d_in, const int* in_sizes, int n_in,
                              void* d_out, int out_size)
{
    const int*   train_types    = (const int*)d_in[1];
    const int*   node_neigh     = (const int*)d_in[2];
    const int*   indices        = (const int*)d_in[3];
    const float* user_features  = (const float*)d_in[4];
    const float* text_features  = (const float*)d_in[5];
    const float* neigh_features = (const float*)d_in[6];
    const float* text_embed     = (const float*)d_in[7];
    const float* user_embed     = (const float*)d_in[8];
    const float* tweet_u        = (const float*)d_in[9];
    const float* user_u         = (const float*)d_in[10];
    const float* trans_w        = (const float*)d_in[11];
    const float* s1             = (const float*)d_in[12];
    const float* s2             = (const float*)d_in[13];

    int B  = in_sizes[3];
    int NU = in_sizes[4] / USER_DIM;
    float* out = (float*)d_out;

    const int k2_smem = (K2_SMEM > TR_SMEM ? K2_SMEM : TR_SMEM) * 4;
    cudaFuncSetAttribute(k_fused, cudaFuncAttributeMaxDynamicSharedMemorySize,
                         k2_smem);
    const int k3_smem = K3_SMEM * 4;
    cudaFuncSetAttribute(k_final, cudaFuncAttributeMaxDynamicSharedMemorySize,
                         k3_smem);

    int gblocks = (B * 2 + 7) / 8 + 1;
    k_gather_scan<<<gblocks, 256>>>(train_types, node_neigh, neigh_features,
                                    indices, B, NU);

    int Ttr = (B + TR_ROWS - 1) / TR_ROWS;
    int gemmCTAs = ((B + 63) / 64) * NCHUNK;
    k_fused<<<2 * Ttr + gemmCTAs, 320, k2_smem>>>(
        tweet_u, user_u, s1, s2, indices, text_features, text_embed,
        B, NU, Ttr);

    k_final<<<(B + 31) / 32, 256, k3_smem>>>(out, indices, user_features,
                                             user_embed, trans_w, B, NU);
}

// round 17
// speedup vs baseline: 1.1432x; 1.1432x over previous
#include <cuda_runtime.h>
#include <math.h>
#include <stdint.h>

// ---------------------------------------------------------------------------
// GATNE forward v11 (v9 skeleton + vectorized 400-thread GEMM):
//   k_gather_scan : block0 = partition scan; rest = neighbor gather (v2 form)
//   k_trans       : sequential-t single-U-buffer, no min-blocks
//   k_gemm6       : BM=64 x BN=200, 400 thr (8x50), thread tile 8x4, ALL
//                   smem reads LDS.128; cp.async double-buffered
//   k_reduce      : sum 7 partials per text row, normalize, write
// ---------------------------------------------------------------------------

#define EMB       200
#define EMBU      20
#define TEXT_DIM  768
#define USER_DIM  32
#define NSLOT     10
#define B_MAX     4096
#define NCHUNK    7

// gemm smem layout (floats)
#define AM_LD     44
#define AM_BUF    (64 * AM_LD)
#define OFF_AM    0
#define OFF_BS    (2 * AM_BUF)
#define BS_BUF    (40 * EMB)
#define OFF_SNRM  (OFF_BS + 2 * BS_BUF)
#define OFF_SROW  (OFF_SNRM + 64)
#define OFF_SIDX  (OFF_SROW + 64)
#define GEMM_SMEM_FLOATS (OFF_SIDX + 64)
#define GTH       400

// ------------------------- device scratch ----------------------------------
__device__ int    g_rowmap[B_MAX];
__device__ int    g_tmap[B_MAX];
__device__ int    g_nuser;
__device__ int    g_ntype0;
__device__ float  g_agg[B_MAX * 40];
__device__ float4 g_nsum4[B_MAX * 2 * (TEXT_DIM / 4)];
__device__ float  g_part[(size_t)NCHUNK * B_MAX * EMB];

// ------------------------- cp.async helpers ---------------------------------
__device__ __forceinline__ void cp16(void* dst, const void* src)
{
    uint32_t d = (uint32_t)__cvta_generic_to_shared(dst);
    asm volatile("cp.async.cg.shared.global [%0], [%1], 16;\n"
                 :: "r"(d), "l"(src));
}
__device__ __forceinline__ void cp_commit()
{
    asm volatile("cp.async.commit_group;\n");
}
template<int N> __device__ __forceinline__ void cp_wait()
{
    asm volatile("cp.async.wait_group %0;\n" :: "n"(N));
}

// ------------------------- k1: gather + fused scan ---------------------------
__global__ __launch_bounds__(256) void k_gather_scan(
    const int*   __restrict__ train_types,
    const int*   __restrict__ node_neigh,
    const float* __restrict__ neigh_features,
    const int*   __restrict__ indices,
    int B, int NU)
{
    int tid  = threadIdx.x;
    int lane = tid & 31;
    int wid  = tid >> 5;

    if (blockIdx.x == 0) {
        __shared__ int wsU[8], wsT[8];
        const int CH = 16;
        int b0 = tid * CH;
        int idxv[CH], tyv[CH];
        int cu = 0, ct = 0;
#pragma unroll
        for (int j = 0; j < CH; j++) {
            int b = b0 + j;
            if (b < B) {
                idxv[j] = indices[b];
                tyv[j]  = train_types[b];
                cu += (idxv[j] < NU);
                ct += (tyv[j] == 0);
            }
        }
        int xu = cu, xt = ct;
        for (int o = 1; o < 32; o <<= 1) {
            int yu = __shfl_up_sync(0xffffffffu, xu, o);
            int yt = __shfl_up_sync(0xffffffffu, xt, o);
            if (lane >= o) { xu += yu; xt += yt; }
        }
        if (lane == 31) { wsU[wid] = xu; wsT[wid] = xt; }
        __syncthreads();
        int baseU = 0, baseT = 0, totU = 0, totT = 0;
#pragma unroll
        for (int i = 0; i < 8; i++) {
            if (i < wid) { baseU += wsU[i]; baseT += wsT[i]; }
            totU += wsU[i]; totT += wsT[i];
        }
        int uRun = (xu - cu) + baseU;
        int tRun = (xt - ct) + baseT;
#pragma unroll
        for (int j = 0; j < CH; j++) {
            int b = b0 + j;
            if (b >= B) break;
            if (idxv[j] < NU) g_rowmap[uRun++] = b;
            else              g_rowmap[totU + (b - uRun)] = b;
            if (tyv[j] == 0)  g_tmap[tRun++] = b;
            else              g_tmap[totT + (b - tRun)] = b;
        }
        if (tid == 0) { g_nuser = totU; g_ntype0 = totT; }
        return;
    }

    int gw = (blockIdx.x - 1) * 8 + wid;
    int b  = gw >> 1;
    int t  = gw & 1;
    if (b >= B) return;

    int ty = train_types[b];
    int nn_l = 0;
    if (lane < NSLOT)
        nn_l = node_neigh[(size_t)(b * 2 + t) * NSLOT + lane];

    const float4* nf4 = (const float4*)neigh_features;
    float4* dst = g_nsum4 + (size_t)(b * 2 + t) * 192;

    if (ty == 1) {
#pragma unroll 2
        for (int c = 0; c < 6; c++) {
            int k4 = c * 32 + lane;
            float4 acc = make_float4(0.f, 0.f, 0.f, 0.f);
#pragma unroll
            for (int s = 0; s < NSLOT; s++) {
                int idx = __shfl_sync(0xffffffffu, nn_l, s);
                float4 v = nf4[(size_t)idx * 192 + k4];
                acc.x += v.x; acc.y += v.y; acc.z += v.z; acc.w += v.w;
            }
            dst[k4] = acc;
        }
    } else {
        float4 acc = make_float4(0.f, 0.f, 0.f, 0.f);
#pragma unroll
        for (int s = 0; s < NSLOT; s++) {
            int idx = __shfl_sync(0xffffffffu, nn_l, s);
            if (lane < 8) {
                float4 v = nf4[(size_t)idx * 192 + lane];
                acc.x += v.x; acc.y += v.y; acc.z += v.z; acc.w += v.w;
            }
        }
        if (lane < 8) dst[lane] = acc;
    }
}

// ------------------------- k_trans (v9 form) ---------------------------------
__global__ __launch_bounds__(256) void k_trans(
    const float* __restrict__ tweet_u,
    const float* __restrict__ user_u,
    const float* __restrict__ s1,
    const float* __restrict__ s2,
    int B, int T)
{
    extern __shared__ float sm[];
    float* U1  = sm;                        // [F][20]
    float* nte = U1 + TEXT_DIM * EMBU;      // [32][40]
    int*  srow = (int*)(nte + 32 * 40);     // [32]

    int tid  = threadIdx.x;
    int wid  = tid >> 5;
    int lane = tid & 31;

    int ty   = (blockIdx.x >= T) ? 1 : 0;
    int tile = ty ? (blockIdx.x - T) : blockIdx.x;
    int n0   = g_ntype0;
    int base = ty ? n0 : 0;
    int cnt  = ty ? (B - n0) : n0;
    int m0   = tile * 32;
    if (m0 >= cnt) return;

    int F = ty ? TEXT_DIM : USER_DIM;
    const float* Usrc = ty ? tweet_u : user_u;

    if (tid < 32) {
        int mm = m0 + tid; if (mm > cnt - 1) mm = cnt - 1;
        srow[tid] = g_tmap[base + mm];
    }

    int i0 = 4 * wid;
    const float* ns = (const float*)g_nsum4;

    for (int t = 0; t < 2; t++) {
        __syncthreads();
        {
            int cnt4 = (F * EMBU) / 4;
            const float4* src = (const float4*)(Usrc + (size_t)t * F * EMBU);
            float4* d = (float4*)U1;
            for (int i = tid; i < cnt4; i += 256) d[i] = src[i];
        }
        __syncthreads();

        int br[4];
#pragma unroll
        for (int r = 0; r < 4; r++) br[r] = srow[i0 + r];

        float acc[4][EMBU];
#pragma unroll
        for (int r = 0; r < 4; r++)
#pragma unroll
            for (int u = 0; u < EMBU; u++) acc[r][u] = 0.f;
        const float* nsr[4];
#pragma unroll
        for (int r = 0; r < 4; r++)
            nsr[r] = ns + (size_t)(br[r] * 2 + t) * TEXT_DIM;

        for (int k = lane; k < F; k += 32) {
            float a0 = nsr[0][k], a1 = nsr[1][k];
            float a2 = nsr[2][k], a3 = nsr[3][k];
            const float4* Urow = (const float4*)(U1 + k * EMBU);
#pragma unroll
            for (int q = 0; q < 5; q++) {
                float4 uv = Urow[q];
                acc[0][q*4+0] += a0 * uv.x; acc[1][q*4+0] += a1 * uv.x;
                acc[2][q*4+0] += a2 * uv.x; acc[3][q*4+0] += a3 * uv.x;
                acc[0][q*4+1] += a0 * uv.y; acc[1][q*4+1] += a1 * uv.y;
                acc[2][q*4+1] += a2 * uv.y; acc[3][q*4+1] += a3 * uv.y;
                acc[0][q*4+2] += a0 * uv.z; acc[1][q*4+2] += a1 * uv.z;
                acc[2][q*4+2] += a2 * uv.z; acc[3][q*4+2] += a3 * uv.z;
                acc[0][q*4+3] += a0 * uv.w; acc[1][q*4+3] += a1 * uv.w;
                acc[2][q*4+3] += a2 * uv.w; acc[3][q*4+3] += a3 * uv.w;
            }
        }
#pragma unroll
        for (int r = 0; r < 4; r++)
#pragma unroll
            for (int u = 0; u < EMBU; u++) {
                float v = acc[r][u];
                for (int o = 16; o; o >>= 1)
                    v += __shfl_xor_sync(0xffffffffu, v, o);
                if (lane == 0) nte[(i0 + r) * 40 + t * EMBU + u] = v;
            }
    }
    __syncthreads();

    const float* S1 = s1 + ty * (EMBU * EMBU);
    const float* S2 = s2 + ty * EMBU;
    for (int g = wid; g < 32; g += 8) {
        if (m0 + g >= cnt) continue;
        int b = srow[g];
        float sc[2];
#pragma unroll
        for (int t = 0; t < 2; t++) {
            float h = 0.f;
            if (lane < EMBU) {
#pragma unroll
                for (int u = 0; u < EMBU; u++)
                    h += nte[g * 40 + t * EMBU + u] * S1[u * EMBU + lane];
                h = tanhf(h) * S2[lane];
            }
            for (int o = 16; o; o >>= 1) h += __shfl_xor_sync(0xffffffffu, h, o);
            sc[t] = h;
        }
        float m  = fmaxf(sc[0], sc[1]);
        float e0 = expf(sc[0] - m);
        float e1 = expf(sc[1] - m);
        float inv = 1.f / (e0 + e1);
        float a0 = e0 * inv, a1 = e1 * inv;
        for (int l = lane; l < 40; l += 32) {
            float v = 0.f;
            if ((l / EMBU) == ty) {
                int u = l - (l / EMBU) * EMBU;
                v = a0 * nte[g * 40 + u] + a1 * nte[g * 40 + EMBU + u];
            }
            g_agg[(size_t)b * 40 + l] = v;
        }
    }
}

// ------------------------- k_gemm6: 400 thr, 8x4 tile, LDS.128 ---------------
__global__ __launch_bounds__(GTH, 2) void k_gemm6(
    float* __restrict__ out,
    const int*   __restrict__ indices,
    const float* __restrict__ user_features,
    const float* __restrict__ text_features,
    const float* __restrict__ user_embed,
    const float* __restrict__ text_embed,
    const float* __restrict__ trans_w,
    int B, int NU, int utiles)
{
    extern __shared__ float sm[];
    float* Am   = sm + OFF_AM;      // [2][64][AM_LD] m-major
    float* Bsm  = sm + OFF_BS;      // [2][40][EMB]
    float* snrm = sm + OFF_SNRM;
    int*   srow = (int*)(sm + OFF_SROW);
    int*   sidx = (int*)(sm + OFF_SIDX);

    int bx = blockIdx.x;
    int cls, tm, chunk, kt0, ntk;
    if (bx < utiles) { cls = 0; tm = bx; chunk = 0; kt0 = 0; ntk = 2; }
    else {
        int r = bx - utiles;
        tm = r / NCHUNK; chunk = r - tm * NCHUNK;
        cls = 1; kt0 = chunk * 3; ntk = 3;
    }
    int nuser = g_nuser;
    int base  = cls ? nuser : 0;
    int cnt   = cls ? (B - nuser) : nuser;
    int m0    = tm * 64;
    if (m0 >= cnt) return;

    int tid = threadIdx.x;
    if (tid < 64) {
        int mm = m0 + tid; if (mm > cnt - 1) mm = cnt - 1;
        int b = g_rowmap[base + mm];
        srow[tid] = b;
        sidx[tid] = indices[b];
    }
    __syncthreads();

    auto loadA = [&](int kt, int buf) {
        float* dstb = Am + buf * AM_BUF;
        int k0 = kt * 40;
        for (int i = tid; i < 640; i += GTH) {
            int m  = i / 10;
            int j4 = i - m * 10;
            int kk = k0 + j4 * 4;
            float* d = dstb + m * AM_LD + j4 * 4;
            int b = srow[m], idx = sidx[m];
            if (cls == 0) {
                if (kk < USER_DIM)
                    cp16(d, user_features + (size_t)idx * USER_DIM + kk);
                else if (kk < 72)
                    cp16(d, g_agg + (size_t)b * 40 + (kk - USER_DIM));
                else
                    *(float4*)d = make_float4(0.f, 0.f, 0.f, 0.f);
            } else {
                if (kk < USER_DIM)
                    *(float4*)d = make_float4(0.f, 0.f, 0.f, 0.f);
                else if (kk < 72)
                    cp16(d, g_agg + (size_t)b * 40 + (kk - USER_DIM));
                else
                    cp16(d, text_features + (size_t)(idx - NU) * TEXT_DIM + (kk - 72));
            }
        }
    };
    auto loadB = [&](int kt, int buf) {
        float* dstb = Bsm + buf * BS_BUF;
        int k0 = kt * 40;
        for (int i = tid; i < 2000; i += GTH) {
            int k  = i / 50;
            int j4 = i - k * 50;
            int kk = k0 + k;
            const float* src;
            if (kk < USER_DIM)      src = user_embed + (size_t)kk * EMB;
            else if (kk < 72)       src = trans_w + (size_t)(kk - USER_DIM) * EMB;
            else                    src = text_embed + (size_t)(kk - 72) * EMB;
            cp16(dstb + k * EMB + j4 * 4, src + j4 * 4);
        }
    };

    int rg = tid / 50;            // 0..7  (8 rows each)
    int cg = tid - rg * 50;       // 0..49 (4 cols each)

    float acc[8][4];
#pragma unroll
    for (int i = 0; i < 8; i++)
#pragma unroll
        for (int j = 0; j < 4; j++) acc[i][j] = 0.f;

    loadA(kt0, 0); loadB(kt0, 0); cp_commit();

    for (int t = 0; t < ntk; t++) {
        int buf = t & 1;
        if (t + 1 < ntk) {
            loadA(kt0 + t + 1, buf ^ 1);
            loadB(kt0 + t + 1, buf ^ 1);
            cp_commit();
            cp_wait<1>();
        } else {
            cp_wait<0>();
        }
        __syncthreads();

        const float* A  = Am + buf * AM_BUF + rg * 8 * AM_LD;
        const float* Bt = Bsm + buf * BS_BUF + cg * 4;
#pragma unroll
        for (int k4 = 0; k4 < 10; k4++) {
            int k = 4 * k4;
            float4 b0 = *(const float4*)(Bt + (k + 0) * EMB);
            float4 b1 = *(const float4*)(Bt + (k + 1) * EMB);
            float4 b2 = *(const float4*)(Bt + (k + 2) * EMB);
            float4 b3 = *(const float4*)(Bt + (k + 3) * EMB);
#pragma unroll
            for (int i = 0; i < 8; i++) {
                float4 a4 = *(const float4*)(A + i * AM_LD + k);
                acc[i][0] += a4.x * b0.x + a4.y * b1.x + a4.z * b2.x + a4.w * b3.x;
                acc[i][1] += a4.x * b0.y + a4.y * b1.y + a4.z * b2.y + a4.w * b3.y;
                acc[i][2] += a4.x * b0.z + a4.y * b1.z + a4.z * b2.z + a4.w * b3.z;
                acc[i][3] += a4.x * b0.w + a4.y * b1.w + a4.z * b2.w + a4.w * b3.w;
            }
        }
        __syncthreads();
    }

    if (cls == 0) {
        // fused normalize; reuse Am region as ssP[64][51]
        float* ssP = Am;
#pragma unroll
        for (int r = 0; r < 8; r++) {
            float s = 0.f;
#pragma unroll
            for (int j = 0; j < 4; j++) s += acc[r][j] * acc[r][j];
            ssP[(rg * 8 + r) * 51 + cg] = s;
        }
        __syncthreads();
        if (tid < 64) {
            float s = 0.f;
            for (int c = 0; c < 50; c++) s += ssP[tid * 51 + c];
            snrm[tid] = 1.f / fmaxf(sqrtf(s), 1e-12f);
        }
        __syncthreads();
#pragma unroll
        for (int r = 0; r < 8; r++) {
            int m = rg * 8 + r;
            if (m0 + m < cnt) {
                float sc = snrm[m];
                float* o = out + (size_t)srow[m] * EMB + cg * 4;
#pragma unroll
                for (int j = 0; j < 4; j++) o[j] = acc[r][j] * sc;
            }
        }
    } else {
        float* pb = g_part + (size_t)chunk * B_MAX * EMB;
#pragma unroll
        for (int r = 0; r < 8; r++) {
            int m = rg * 8 + r;
            int mr = m0 + m;
            if (mr < cnt) {
                float* p = pb + (size_t)mr * EMB + cg * 4;
#pragma unroll
                for (int j = 0; j < 4; j++) p[j] = acc[r][j];
            }
        }
    }
}

// ------------------------- reduce partials + normalize -----------------------
__global__ __launch_bounds__(256) void k_reduce(float* __restrict__ out, int B)
{
    __shared__ float ws[8];
    int i = blockIdx.x;
    int nuser = g_nuser;
    int ntext = B - nuser;
    if (i >= ntext) return;
    int b = g_rowmap[nuser + i];
    int tid = threadIdx.x;

    float v = 0.f;
    if (tid < EMB) {
#pragma unroll
        for (int c = 0; c < NCHUNK; c++)
            v += g_part[(size_t)c * B_MAX * EMB + (size_t)i * EMB + tid];
    }
    float s = v * v;
    for (int o = 16; o; o >>= 1) s += __shfl_xor_sync(0xffffffffu, s, o);
    if ((tid & 31) == 0) ws[tid >> 5] = s;
    __syncthreads();
    float tot = 0.f;
#pragma unroll
    for (int w = 0; w < 8; w++) tot += ws[w];
    float sc = 1.f / fmaxf(sqrtf(tot), 1e-12f);
    if (tid < EMB) out[(size_t)b * EMB + tid] = v * sc;
}

// ------------------------- launch ------------------------------------------
extern "C" void kernel_launch(void* const* d_in, const int* in_sizes, int n_in,
                              void* d_out, int out_size)
{
    const int*   train_types    = (const int*)d_in[1];
    const int*   node_neigh     = (const int*)d_in[2];
    const int*   indices        = (const int*)d_in[3];
    const float* user_features  = (const float*)d_in[4];
    const float* text_features  = (const float*)d_in[5];
    const float* neigh_features = (const float*)d_in[6];
    const float* text_embed     = (const float*)d_in[7];
    const float* user_embed     = (const float*)d_in[8];
    const float* tweet_u        = (const float*)d_in[9];
    const float* user_u         = (const float*)d_in[10];
    const float* trans_w        = (const float*)d_in[11];
    const float* s1             = (const float*)d_in[12];
    const float* s2             = (const float*)d_in[13];

    int B  = in_sizes[3];
    int NU = in_sizes[4] / USER_DIM;
    float* out = (float*)d_out;

    const int trans_smem = (TEXT_DIM * EMBU + 32 * 40) * 4 + 32 * 4;
    cudaFuncSetAttribute(k_trans, cudaFuncAttributeMaxDynamicSharedMemorySize,
                         trans_smem);
    const int gemm_smem = GEMM_SMEM_FLOATS * 4;
    cudaFuncSetAttribute(k_gemm6, cudaFuncAttributeMaxDynamicSharedMemorySize,
                         gemm_smem);

    int gblocks = (B * 2 + 7) / 8 + 1;
    k_gather_scan<<<gblocks, 256>>>(train_types, node_neigh, neigh_features,
                                    indices, B, NU);

    int T = (B + 31) / 32;
    k_trans<<<2 * T, 256, trans_smem>>>(tweet_u, user_u, s1, s2, B, T);

    int utiles = (B + 63) / 64;
    k_gemm6<<<utiles * (1 + NCHUNK), GTH, gemm_smem>>>(
        out, indices, user_features, text_features, user_embed,
        text_embed, trans_w, B, NU, utiles);

    k_reduce<<<B, 256>>>(out, B);
}